// round 4
// baseline (speedup 1.0000x reference)
#include <cuda_runtime.h>
#include <cuda_bf16.h>
#include <cstddef>

#define E_TOT 512
#define Dd    64
#define Hh    256
#define Nn    16
#define Aa    8
#define Tt    128
#define HO    (Nn + Aa * Nn)   // 144 head outputs

#define SF2   0.01f
#define SN2   0.01f
#define NEG_HALF_INV_L2 (-50.0f)   // -0.5 / 0.1^2

// ---------------------------------------------------------------------------
// Single fused kernel: block = one environment e.
//   Phase A: in-block MLP via warp-reduce dots (coalesced weight rows).
//   Phase B: warp 0 Gauss-Jordan inverse (syncwarp only) || warps 1-7 Ks/kssd.
//   Phase C: U = Ks K^-1, mu, and cov (computed once, stored 8x, coalesced).
// ---------------------------------------------------------------------------
__global__ __launch_bounds__(256)
void fused_kernel(const float* __restrict__ x,
                  const float* __restrict__ W1, const float* __restrict__ b1,
                  const float* __restrict__ W2, const float* __restrict__ b2,
                  const float* __restrict__ Wt, const float* __restrict__ bt,
                  const float* __restrict__ Wa, const float* __restrict__ ba,
                  const float* __restrict__ tq_g,
                  float* __restrict__ out_mu,
                  float* __restrict__ out_cov)
{
    __shared__ float xs[Dd];
    __shared__ float h1s[Hh];
    __shared__ float h2s[Hh];
    __shared__ float tq[Tt];
    __shared__ float kssd[Tt];               // Kss[i][j] == kssd[|i-j|]
    __shared__ float tt[Nn];
    __shared__ float ys[Aa][Nn];
    __shared__ float Aug[Nn][2 * Nn + 1];    // [K | I] -> [I | K^-1], pad 33
    __shared__ float St[Nn][Tt + 4];         // Ks transposed, pad 132
    __shared__ float U[Tt][Nn + 1];          // U = Ks @ K^-1, pad 17

    const int e    = blockIdx.x;
    const int tid  = threadIdx.x;
    const int wid  = tid >> 5;
    const int lane = tid & 31;

    if (tid < Dd)       xs[tid] = x[e * Dd + tid];
    if (tid < Tt)       tq[tid] = tq_g[tid];
    __syncthreads();

    // ================= Phase A: MLP (warp-reduce, coalesced rows) ==========
    // layer 1: 256 outputs, k=64 split over lanes (2 per lane)
    {
        const float xv0 = xs[lane];
        const float xv1 = xs[lane + 32];
        #pragma unroll 4
        for (int i = 0; i < 32; i++) {
            const int o = wid * 32 + i;
            const float* w = W1 + o * Dd;
            float p = w[lane] * xv0 + w[lane + 32] * xv1;   // 2x coalesced LDG
            p += __shfl_xor_sync(0xffffffffu, p, 16);
            p += __shfl_xor_sync(0xffffffffu, p, 8);
            p += __shfl_xor_sync(0xffffffffu, p, 4);
            p += __shfl_xor_sync(0xffffffffu, p, 2);
            p += __shfl_xor_sync(0xffffffffu, p, 1);
            if (lane == 0) h1s[o] = tanhf(p + b1[o]);
        }
    }
    __syncthreads();

    // layer 2: 256 outputs, k=256 split over lanes (8 per lane, stride 32)
    {
        float hv[8];
        #pragma unroll
        for (int j = 0; j < 8; j++) hv[j] = h1s[j * 32 + lane];  // hoisted, cf-free
        #pragma unroll 4
        for (int i = 0; i < 32; i++) {
            const int o = wid * 32 + i;
            const float* w = W2 + o * Hh;
            float p = 0.0f;
            #pragma unroll
            for (int j = 0; j < 8; j++) p += w[j * 32 + lane] * hv[j]; // coalesced
            p += __shfl_xor_sync(0xffffffffu, p, 16);
            p += __shfl_xor_sync(0xffffffffu, p, 8);
            p += __shfl_xor_sync(0xffffffffu, p, 4);
            p += __shfl_xor_sync(0xffffffffu, p, 2);
            p += __shfl_xor_sync(0xffffffffu, p, 1);
            if (lane == 0) h2s[o] = tanhf(p + b2[o]);
        }
    }
    __syncthreads();

    // heads: 144 outputs (16 times + 128 anchors), 18 per warp
    {
        float gv[8];
        #pragma unroll
        for (int j = 0; j < 8; j++) gv[j] = h2s[j * 32 + lane];
        #pragma unroll 2
        for (int i = 0; i < 18; i++) {
            const int q = wid * 18 + i;                       // 0..143
            const float* w = (q < Nn) ? (Wt + q * Hh) : (Wa + (q - Nn) * Hh);
            float p = 0.0f;
            #pragma unroll
            for (int j = 0; j < 8; j++) p += w[j * 32 + lane] * gv[j];
            p += __shfl_xor_sync(0xffffffffu, p, 16);
            p += __shfl_xor_sync(0xffffffffu, p, 8);
            p += __shfl_xor_sync(0xffffffffu, p, 4);
            p += __shfl_xor_sync(0xffffffffu, p, 2);
            p += __shfl_xor_sync(0xffffffffu, p, 1);
            if (lane == 0) {
                if (q < Nn) tt[q] = p + bt[q];
                else {
                    int r = q - Nn;
                    ys[r >> 4][r & 15] = p + ba[r];
                }
            }
        }
    }
    __syncthreads();

    // ============ Phase B: warp 0 GJ inverse || warps 1-7 Ks + kssd ========
    if (wid == 0) {
        #pragma unroll
        for (int r = 0; r < 8; r++) {
            int idx = r * 32 + lane;
            int i = idx >> 4, j = idx & 15;
            float d = tt[i] - tt[j];
            float v = SF2 * __expf(NEG_HALF_INV_L2 * d * d);
            if (i == j) v += SN2;
            Aug[i][j] = v;
            Aug[i][Nn + j] = (i == j) ? 1.0f : 0.0f;
        }
        __syncwarp();
        for (int k = 0; k < Nn; k++) {
            float pinv = 1.0f / Aug[k][k];
            float rowk = Aug[k][lane] * pinv;
            Aug[k][lane] = rowk;
            __syncwarp();
            #pragma unroll
            for (int i = 0; i < Nn; i++) {
                if (i != k) {
                    float c = Aug[i][k];       // LDS precedes STS in the stream
                    Aug[i][lane] -= c * rowk;
                }
            }
            __syncwarp();
        }
    } else {
        for (int idx = tid - 32; idx < Tt * Nn; idx += 224) {
            int j = idx >> 4, n = idx & 15;
            float d = tq[j] - tt[n];
            St[n][j] = SF2 * __expf(NEG_HALF_INV_L2 * d * d);
        }
        if (tid >= 32 && tid < 32 + Tt) {
            int j = tid - 32;
            float d = tq[j] - tq[0];
            kssd[j] = SF2 * __expf(NEG_HALF_INV_L2 * d * d);
        }
    }
    __syncthreads();

    // ==================== Phase C: U, mu, cov ==============================
    // U[i][n] = sum_m Ks[i][m] * Kinv[m][n]
    for (int idx = tid; idx < Tt * Nn; idx += 256) {
        int i = idx >> 4, n = idx & 15;
        float s = 0.0f;
        #pragma unroll
        for (int m = 0; m < Nn; m++) s += St[m][i] * Aug[m][Nn + n];
        U[i][n] = s;
    }
    __syncthreads();

    // mu[a][i] = dot16(U[i], y[a])
    for (int idx = tid; idx < Aa * Tt; idx += 256) {
        int a = idx >> 7, i = idx & 127;
        float s = 0.0f;
        #pragma unroll
        for (int n = 0; n < Nn; n++) s += U[i][n] * ys[a][n];
        out_mu[((size_t)e * Aa + a) * Tt + i] = s;
    }

    // cov[i][j] = kssd[|i-j|] - dot16(U[i], Ks[j]); stored 8x, coalesced
    const int j0 = lane * 4;
    for (int step = 0; step < Tt / 8; step++) {
        int i = step * 8 + wid;
        float u[Nn];
        #pragma unroll
        for (int n = 0; n < Nn; n++) u[n] = U[i][n];   // broadcast LDS
        float a0 = 0.f, a1 = 0.f, a2 = 0.f, a3 = 0.f;
        #pragma unroll
        for (int n = 0; n < Nn; n++) {
            float4 s4 = *(const float4*)&St[n][j0];    // conflict-free LDS.128
            float un = u[n];
            a0 += un * s4.x; a1 += un * s4.y; a2 += un * s4.z; a3 += un * s4.w;
        }
        int d0 = i - j0;       d0 = d0 < 0 ? -d0 : d0;
        int d1 = i - (j0 + 1); d1 = d1 < 0 ? -d1 : d1;
        int d2 = i - (j0 + 2); d2 = d2 < 0 ? -d2 : d2;
        int d3 = i - (j0 + 3); d3 = d3 < 0 ? -d3 : d3;
        float4 v;
        v.x = kssd[d0] - a0;
        v.y = kssd[d1] - a1;
        v.z = kssd[d2] - a2;
        v.w = kssd[d3] - a3;
        size_t base = (((size_t)e * Aa) * Tt + i) * Tt + j0;
        #pragma unroll
        for (int a = 0; a < Aa; a++)
            *(float4*)&out_cov[base + (size_t)a * Tt * Tt] = v;   // coalesced STG.128
    }
}

// ---------------------------------------------------------------------------
extern "C" void kernel_launch(void* const* d_in, const int* in_sizes, int n_in,
                              void* d_out, int out_size)
{
    const float* x  = (const float*)d_in[0];
    // d_in[1] = a, d_in[2] = da (unused by reference)
    const float* W1 = (const float*)d_in[3];
    const float* b1 = (const float*)d_in[4];
    const float* W2 = (const float*)d_in[5];
    const float* b2 = (const float*)d_in[6];
    const float* Wt = (const float*)d_in[7];
    const float* bt = (const float*)d_in[8];
    const float* Wa = (const float*)d_in[9];
    const float* ba = (const float*)d_in[10];
    const float* tq = (const float*)d_in[11];

    float* out     = (float*)d_out;
    float* out_mu  = out;                                   // E*A*T floats
    float* out_cov = out + (size_t)E_TOT * Aa * Tt;         // E*A*T*T floats

    fused_kernel<<<E_TOT, 256>>>(x, W1, b1, W2, b2, Wt, bt, Wa, ba,
                                 tq, out_mu, out_cov);
}